// round 14
// baseline (speedup 1.0000x reference)
#include <cuda_runtime.h>
#include <math.h>
#include <stdint.h>

#define HH 320
#define WW 320
#define HWSZ (320*320)

// ---------------- scratch (static device globals; no allocation) -------------
__device__ float g_up[3*HWSZ];
__device__ float g_feat[64*HWSZ];
__device__ float g_buf1[64*HWSZ];
__device__ float g_buf2[64*HWSZ];
__device__ float g_hid[32*HWSZ];
__device__ __align__(16) float g_w3t[4*9216];   // 4 transposed 3x3 32->32 [ci][k][co]
__device__ __align__(16) float g_w5a[3*800];    // conv1 5x5 3->32  [ci][k][co]
__device__ __align__(16) float g_w5b[64*800];   // p1    5x5 64->32 [ci][k][co]

typedef unsigned long long u64;

// ---------------- packed f32x2 helpers (sm_103a FFMA2) -----------------------
__device__ __forceinline__ u64 pack2(float a, float b) {
    u64 r; asm("mov.b64 %0,{%1,%2};" : "=l"(r) : "f"(a), "f"(b)); return r;
}
__device__ __forceinline__ void unpack2(u64 v, float& a, float& b) {
    asm("mov.b64 {%0,%1},%2;" : "=f"(a), "=f"(b) : "l"(v));
}
__device__ __forceinline__ u64 fma2(u64 a, u64 b, u64 c) {
    u64 d; asm("fma.rn.f32x2 %0,%1,%2,%3;" : "=l"(d) : "l"(a), "l"(b), "l"(c)); return d;
}

// ---------------- cp.async helpers -------------------------------------------
__device__ __forceinline__ void cp4(uint32_t s, const float* g, bool ok) {
    int sz = ok ? 4 : 0;
    asm volatile("cp.async.ca.shared.global [%0], [%1], 4, %2;"
                 :: "r"(s), "l"(g), "r"(sz) : "memory");
}
__device__ __forceinline__ void cp16(uint32_t s, const float4* g) {
    asm volatile("cp.async.cg.shared.global [%0], [%1], 16;"
                 :: "r"(s), "l"(g) : "memory");
}
#define CP_COMMIT() asm volatile("cp.async.commit_group;" ::: "memory")
#define CP_WAIT(n)  asm volatile("cp.async.wait_group %0;" :: "n"(n) : "memory")

// ---------------- merged weight transpose pre-kernel --------------------------
__global__ void tr_all_k(const float* __restrict__ w0, const float* __restrict__ w1,
                         const float* __restrict__ w2, const float* __restrict__ w3,
                         const float* __restrict__ wa, const float* __restrict__ wb,
                         float* __restrict__ d3, float* __restrict__ da,
                         float* __restrict__ db) {
    int i = blockIdx.x*256 + threadIdx.x;
    if (i < 36864) {
        int n = i / 9216, e = i % 9216;
        const float* srcs[4] = {w0, w1, w2, w3};
        int co = e / 288, rem = e % 288, ci = rem / 9, k = rem % 9;
        d3[n*9216 + ci*288 + k*32 + co] = srcs[n][e];
    } else if (i < 36864 + 2400) {
        int e = i - 36864;
        int co = e / 75, rem = e % 75, ci = rem / 25, k = rem % 25;
        da[ci*800 + k*32 + co] = wa[e];
    } else if (i < 36864 + 2400 + 51200) {
        int e = i - 36864 - 2400;
        int co = e / 1600, rem = e % 1600, ci = rem / 25, k = rem % 25;
        db[ci*800 + k*32 + co] = wb[e];
    }
}

// ---------------- bicubic x2 (A = -0.75) -------------------------------------
__device__ __forceinline__ float cubicw(float t) {
    t = fabsf(t);
    if (t <= 1.0f) return ((1.25f*t - 2.25f)*t)*t + 1.0f;
    if (t <  2.0f) return -0.75f*((((t - 5.0f)*t + 8.0f)*t) - 4.0f);
    return 0.0f;
}

__global__ void bicubic_k(const float* __restrict__ q, float* __restrict__ o) {
    int idx = blockIdx.x*256 + threadIdx.x;
    int ox = idx % 320;
    int t  = idx / 320;
    int oy = t % 320;
    int c  = t / 320;
    float sy = (oy + 0.5f)*0.5f - 0.5f;
    float sx = (ox + 0.5f)*0.5f - 0.5f;
    int iy0 = (int)floorf(sy), ix0 = (int)floorf(sx);
    float wy[4], wx[4]; int jy[4], jx[4];
    #pragma unroll
    for (int k = 0; k < 4; k++) {
        int ty = iy0 - 1 + k;
        wy[k] = cubicw(sy - (float)ty);
        jy[k] = min(max(ty, 0), 159);
        int tx = ix0 - 1 + k;
        wx[k] = cubicw(sx - (float)tx);
        jx[k] = min(max(tx, 0), 159);
    }
    const float* qc = q + c*160*160;
    float s = 0.0f;
    #pragma unroll
    for (int yy = 0; yy < 4; yy++) {
        float acc = 0.0f;
        #pragma unroll
        for (int xx = 0; xx < 4; xx++)
            acc += wx[xx]*__ldg(qc + jy[yy]*160 + jx[xx]);
        s += wy[yy]*acc;
    }
    o[idx] = s;
}

// ---------------- 3x3 conv, 32->32, pad 1, dual image ------------------------
// tile 64x4; thread = 4 px x 8 co; cp.async double-buffered; 4 blocks/SM
#define C3_CHUNK 8
#define C3_RS   68
#define C3_CIS  (6*C3_RS)                    // 408
#define C3_BIN  (C3_CHUNK*C3_CIS)            // 3264
#define C3_BW   (C3_CHUNK*288)               // 2304
#define C3_BUF  (C3_BIN + C3_BW)             // 5568 floats
#define C3_SMEM (2*C3_BUF*4)                 // 44544 B

template<int MODE>
__global__ void __launch_bounds__(256, 4) conv3_k(
    const float* __restrict__ in0, const float* __restrict__ in1,
    const float* __restrict__ wtT, const float* __restrict__ bs,
    const float* __restrict__ sk0, const float* __restrict__ sk1,
    float* __restrict__ out0, float* __restrict__ out1)
{
    extern __shared__ float sm[];
    const uint32_t smem0 = (uint32_t)__cvta_generic_to_shared(sm);
    const float* in = blockIdx.z ? in1 : in0;
    const float* sk = blockIdx.z ? sk1 : sk0;
    float* out      = blockIdx.z ? out1 : out0;
    const int tid = threadIdx.x;
    const int txg = tid & 15;
    const int ty  = (tid >> 4) & 3;
    const int cog = tid >> 6;
    const int ox0 = blockIdx.x*64, oy0 = blockIdx.y*4;

    const int r1 = tid / 66,        c1 = tid % 66;
    const int r2 = (tid+256) / 66,  c2 = (tid+256) % 66;
    const bool has2 = tid < 140;
    const int y1 = oy0 - 1 + r1, x1 = ox0 - 1 + c1;
    const int y2 = oy0 - 1 + r2, x2 = ox0 - 1 + c2;
    const bool ok1 = (y1 >= 0 && y1 < HH && x1 >= 0 && x1 < WW);
    const bool ok2 = has2 && (y2 >= 0 && y2 < HH && x2 >= 0 && x2 < WW);
    const int g1 = ok1 ? (y1*WW + x1) : 0;
    const int g2 = ok2 ? (y2*WW + x2) : 0;
    const int so1 = r1*C3_RS + c1;
    const int so2 = r2*C3_RS + c2;

    auto stage = [&](int nb, int c0) {
        uint32_t sb = smem0 + nb*(C3_BUF*4);
        const float* ip1 = in + c0*HWSZ + g1;
        uint32_t d1 = sb + so1*4;
        #pragma unroll
        for (int ci = 0; ci < C3_CHUNK; ci++)
            cp4(d1 + ci*(C3_CIS*4), ip1 + ci*HWSZ, ok1);
        if (has2) {
            const float* ip2 = in + c0*HWSZ + g2;
            uint32_t d2 = sb + so2*4;
            #pragma unroll
            for (int ci = 0; ci < C3_CHUNK; ci++)
                cp4(d2 + ci*(C3_CIS*4), ip2 + ci*HWSZ, ok2);
        }
        const float4* wsrc = (const float4*)(wtT + c0*288);
        uint32_t wdst = sb + C3_BIN*4;
        cp16(wdst + tid*16,        wsrc + tid);
        cp16(wdst + (tid+256)*16,  wsrc + tid + 256);
        if (tid < 64) cp16(wdst + (tid+512)*16, wsrc + tid + 512);
    };

    u64 acc[4][4];
    #pragma unroll
    for (int cp = 0; cp < 4; cp++) {
        u64 b = pack2(__ldg(bs + cog*8 + 2*cp), __ldg(bs + cog*8 + 2*cp + 1));
        #pragma unroll
        for (int p = 0; p < 4; p++) acc[p][cp] = b;
    }

    stage(0, 0);
    CP_COMMIT();

    const int NCH = 32/C3_CHUNK;
    for (int ch = 0; ch < NCH; ch++) {
        int nb = ch & 1;
        if (ch + 1 < NCH) {
            stage(nb ^ 1, (ch+1)*C3_CHUNK);
            CP_COMMIT();
            CP_WAIT(1);
        } else {
            CP_WAIT(0);
        }
        __syncthreads();

        const float* s_in = sm + nb*C3_BUF;
        const float* s_w  = s_in + C3_BIN;
        for (int ci = 0; ci < C3_CHUNK; ci++) {
            const float* base = s_in + ci*C3_CIS + ty*C3_RS + txg*4;
            const float* wb   = s_w + ci*288 + cog*8;
            #pragma unroll
            for (int ky = 0; ky < 3; ky++) {
                const float* rp = base + ky*C3_RS;
                float4 v4 = *(const float4*)rp;
                float2 v2 = *(const float2*)(rp + 4);
                u64 vp[6];
                vp[0]=pack2(v4.x,v4.x); vp[1]=pack2(v4.y,v4.y); vp[2]=pack2(v4.z,v4.z);
                vp[3]=pack2(v4.w,v4.w); vp[4]=pack2(v2.x,v2.x); vp[5]=pack2(v2.y,v2.y);
                #pragma unroll
                for (int kx = 0; kx < 3; kx++) {
                    const ulonglong2* wq = (const ulonglong2*)(wb + (ky*3 + kx)*32);
                    ulonglong2 w0 = wq[0], w1 = wq[1];
                    u64 w[4] = {w0.x, w0.y, w1.x, w1.y};
                    #pragma unroll
                    for (int p = 0; p < 4; p++)
                        #pragma unroll
                        for (int cp = 0; cp < 4; cp++)
                            acc[p][cp] = fma2(vp[p+kx], w[cp], acc[p][cp]);
                }
            }
        }
        __syncthreads();
    }

    int o = (oy0 + ty)*WW + ox0 + txg*4;
    #pragma unroll
    for (int cp = 0; cp < 4; cp++) {
        int coe = cog*8 + 2*cp;
        float4 ve, vo;
        unpack2(acc[0][cp], ve.x, vo.x);
        unpack2(acc[1][cp], ve.y, vo.y);
        unpack2(acc[2][cp], ve.z, vo.z);
        unpack2(acc[3][cp], ve.w, vo.w);
        if (MODE == 0) {
            ve.x=fmaxf(ve.x,0.f); ve.y=fmaxf(ve.y,0.f); ve.z=fmaxf(ve.z,0.f); ve.w=fmaxf(ve.w,0.f);
            vo.x=fmaxf(vo.x,0.f); vo.y=fmaxf(vo.y,0.f); vo.z=fmaxf(vo.z,0.f); vo.w=fmaxf(vo.w,0.f);
        } else {
            float4 se = *(const float4*)(sk + coe*HWSZ + o);
            float4 so = *(const float4*)(sk + (coe+1)*HWSZ + o);
            ve.x+=se.x; ve.y+=se.y; ve.z+=se.z; ve.w+=se.w;
            vo.x+=so.x; vo.y+=so.y; vo.z+=so.z; vo.w+=so.w;
            ve.x=(ve.x>=0.f)?ve.x:0.2f*ve.x; ve.y=(ve.y>=0.f)?ve.y:0.2f*ve.y;
            ve.z=(ve.z>=0.f)?ve.z:0.2f*ve.z; ve.w=(ve.w>=0.f)?ve.w:0.2f*ve.w;
            vo.x=(vo.x>=0.f)?vo.x:0.2f*vo.x; vo.y=(vo.y>=0.f)?vo.y:0.2f*vo.y;
            vo.z=(vo.z>=0.f)?vo.z:0.2f*vo.z; vo.w=(vo.w>=0.f)?vo.w:0.2f*vo.w;
        }
        *(float4*)(out + coe*HWSZ + o)     = ve;
        *(float4*)(out + (coe+1)*HWSZ + o) = vo;
    }
}

// ---------------- 5x5 conv, CIN->32, pad 2, lrelu, dual image ----------------
// tile 64x4; thread = 4 px x 8 co; 4 blocks/SM (latency-hiding)
#define C5_RS  68
#define C5_CIS (8*C5_RS)    // 544

template<int CIN, int CHUNK>
__global__ void __launch_bounds__(256, 4) conv5_k(
    const float* __restrict__ in0, const float* __restrict__ in1,
    const float* __restrict__ wtT, const float* __restrict__ bs,
    float* __restrict__ out0, float* __restrict__ out1)
{
    constexpr int BIN = CHUNK*C5_CIS;
    constexpr int BW  = CHUNK*800;
    constexpr int BUF = BIN + BW;
    extern __shared__ float sm[];
    const uint32_t smem0 = (uint32_t)__cvta_generic_to_shared(sm);
    const float* in = blockIdx.z ? in1 : in0;
    float* out      = blockIdx.z ? out1 : out0;
    const int tid = threadIdx.x;
    const int txg = tid & 15;
    const int ty  = (tid >> 4) & 3;
    const int cog = tid >> 6;
    const int ox0 = blockIdx.x*64, oy0 = blockIdx.y*4;

    const int ir[3] = { tid/68, (tid+256)/68, (tid+512)/68 };
    const int ic[3] = { tid%68, (tid+256)%68, (tid+512)%68 };
    const bool ihas[3] = { true, true, tid < 32 };
    bool iok[3]; int ig[3], iso[3];
    #pragma unroll
    for (int j = 0; j < 3; j++) {
        int y = oy0 - 2 + ir[j], x = ox0 - 2 + ic[j];
        iok[j] = ihas[j] && (y >= 0 && y < HH && x >= 0 && x < WW);
        ig[j]  = iok[j] ? (y*WW + x) : 0;
        iso[j] = ir[j]*C5_RS + ic[j];
    }

    auto stage = [&](int nb, int c0) {
        uint32_t sb = smem0 + nb*(BUF*4);
        #pragma unroll
        for (int j = 0; j < 3; j++) {
            if (!ihas[j]) continue;
            const float* ip = in + c0*HWSZ + ig[j];
            uint32_t d = sb + iso[j]*4;
            #pragma unroll
            for (int ci = 0; ci < CHUNK; ci++)
                cp4(d + ci*(C5_CIS*4), ip + ci*HWSZ, iok[j]);
        }
        const float4* wsrc = (const float4*)(wtT + c0*800);
        uint32_t wdst = sb + BIN*4;
        #pragma unroll
        for (int j = 0; j < (CHUNK*200 + 255)/256; j++) {
            int i = tid + j*256;
            if (i < CHUNK*200) cp16(wdst + i*16, wsrc + i);
        }
    };

    u64 acc[4][4];
    #pragma unroll
    for (int cp = 0; cp < 4; cp++) {
        u64 b = pack2(__ldg(bs + cog*8 + 2*cp), __ldg(bs + cog*8 + 2*cp + 1));
        #pragma unroll
        for (int p = 0; p < 4; p++) acc[p][cp] = b;
    }

    stage(0, 0);
    CP_COMMIT();

    constexpr int NCH = CIN/CHUNK;
    for (int ch = 0; ch < NCH; ch++) {
        int nb = ch & 1;
        if (ch + 1 < NCH) {
            stage(nb ^ 1, (ch+1)*CHUNK);
            CP_COMMIT();
            CP_WAIT(1);
        } else {
            CP_WAIT(0);
        }
        __syncthreads();

        const float* s_in = sm + nb*BUF;
        const float* s_w  = s_in + BIN;
        for (int ci = 0; ci < CHUNK; ci++) {
            const float* base = s_in + ci*C5_CIS + ty*C5_RS + txg*4;
            const float* wb   = s_w + ci*800 + cog*8;
            #pragma unroll
            for (int ky = 0; ky < 5; ky++) {
                const float* rp = base + ky*C5_RS;
                float4 a4 = *(const float4*)rp;
                float4 b4 = *(const float4*)(rp + 4);
                u64 vp[8];
                vp[0]=pack2(a4.x,a4.x); vp[1]=pack2(a4.y,a4.y); vp[2]=pack2(a4.z,a4.z);
                vp[3]=pack2(a4.w,a4.w); vp[4]=pack2(b4.x,b4.x); vp[5]=pack2(b4.y,b4.y);
                vp[6]=pack2(b4.z,b4.z); vp[7]=pack2(b4.w,b4.w);
                #pragma unroll
                for (int kx = 0; kx < 5; kx++) {
                    const ulonglong2* wq = (const ulonglong2*)(wb + (ky*5 + kx)*32);
                    ulonglong2 w0 = wq[0], w1 = wq[1];
                    u64 w[4] = {w0.x, w0.y, w1.x, w1.y};
                    #pragma unroll
                    for (int p = 0; p < 4; p++)
                        #pragma unroll
                        for (int cp = 0; cp < 4; cp++)
                            acc[p][cp] = fma2(vp[p+kx], w[cp], acc[p][cp]);
                }
            }
        }
        __syncthreads();
    }

    int o = (oy0 + ty)*WW + ox0 + txg*4;
    #pragma unroll
    for (int cp = 0; cp < 4; cp++) {
        int coe = cog*8 + 2*cp;
        float4 ve, vo;
        unpack2(acc[0][cp], ve.x, vo.x);
        unpack2(acc[1][cp], ve.y, vo.y);
        unpack2(acc[2][cp], ve.z, vo.z);
        unpack2(acc[3][cp], ve.w, vo.w);
        ve.x=(ve.x>=0.f)?ve.x:0.2f*ve.x; ve.y=(ve.y>=0.f)?ve.y:0.2f*ve.y;
        ve.z=(ve.z>=0.f)?ve.z:0.2f*ve.z; ve.w=(ve.w>=0.f)?ve.w:0.2f*ve.w;
        vo.x=(vo.x>=0.f)?vo.x:0.2f*vo.x; vo.y=(vo.y>=0.f)?vo.y:0.2f*vo.y;
        vo.z=(vo.z>=0.f)?vo.z:0.2f*vo.z; vo.w=(vo.w>=0.f)?vo.w:0.2f*vo.w;
        *(float4*)(out + coe*HWSZ + o)     = ve;
        *(float4*)(out + (coe+1)*HWSZ + o) = vo;
    }
}

// ---------------- fused 1x1 affine head + deformable sampler (4-way split) ----
__device__ __forceinline__ int reflect_idx(int i) {
    int r = i - 1;
    r = (r < 0) ? -r : r;
    r = (r > 319) ? (638 - r) : r;
    return r;
}

__global__ void sampler_k(const float* __restrict__ hid, const float* __restrict__ w2,
                          const float* __restrict__ b2, const float* __restrict__ x,
                          float* __restrict__ out) {
    __shared__ float s_w2[96];
    int tid = threadIdx.x;
    if (tid < 96) s_w2[tid] = w2[tid];
    __syncthreads();
    int p = blockIdx.x*256 + tid;
    int h = p / WW, w = p % WW;
    int cbase = blockIdx.y*16;

    float a0 = __ldg(b2 + 0), a1 = __ldg(b2 + 1), a2 = __ldg(b2 + 2);
    #pragma unroll 4
    for (int c = 0; c < 32; c++) {
        float hv = hid[c*HWSZ + p];
        a0 += hv*s_w2[c];
        a1 += hv*s_w2[32 + c];
        a2 += hv*s_w2[64 + c];
    }
    a0 = fminf(fmaxf(a0 + 1.0f, -3.0f), 3.0f);
    a1 = fminf(fmaxf(a1 + 1.0f, -3.0f), 3.0f);
    a2 = fminf(fmaxf(a2 + 1.0f, -3.0f), 3.0f);
    float th = (a2 - 1.0f)*1.0472f;
    float ct = cosf(th), st = sinf(th);

    int   idx[16];
    float wg[16];
    #pragma unroll
    for (int k = 0; k < 4; k++) {
        float pnx = (k & 2) ? 0.5f : -0.5f;
        float pny = (k & 1) ? 0.5f : -0.5f;
        float px = pnx*a0, py = pny*a1;
        float rx = px*ct - py*st;
        float ry = px*st + py*ct;
        float p_x = rx + 0.5f + (float)(h + 1);
        float p_y = ry + 0.5f + (float)(w + 1);
        float ltx = floorf(p_x), lty = floorf(p_y);
        float ltxc = fminf(fmaxf(ltx,        0.0f), 321.0f);
        float ltyc = fminf(fmaxf(lty,        0.0f), 321.0f);
        float rbxc = fminf(fmaxf(ltx + 1.0f, 0.0f), 321.0f);
        float rbyc = fminf(fmaxf(lty + 1.0f, 0.0f), 321.0f);
        float pxc  = fminf(fmaxf(p_x,        0.0f), 321.0f);
        float pyc  = fminf(fmaxf(p_y,        0.0f), 321.0f);
        float wlx = 1.0f + ltxc - pxc;
        float wrx = 1.0f - (rbxc - pxc);
        float wly = 1.0f + ltyc - pyc;
        float wry = 1.0f - (rbyc - pyc);
        int rl = reflect_idx((int)ltxc);
        int rr = reflect_idx((int)rbxc);
        int cl = reflect_idx((int)ltyc);
        int cr = reflect_idx((int)rbyc);
        idx[k*4+0] = rl*WW + cl;  wg[k*4+0] = wlx*wly;
        idx[k*4+1] = rr*WW + cr;  wg[k*4+1] = wrx*wry;
        idx[k*4+2] = rl*WW + cr;  wg[k*4+2] = wlx*wry;
        idx[k*4+3] = rr*WW + cl;  wg[k*4+3] = wrx*wly;
    }

    int ob = (2*h)*640 + 2*w;
    for (int c = cbase; c < cbase + 16; c++) {
        const float* xc = x + c*HWSZ;
        float* oc = out + c*640*640;
        float v[4];
        #pragma unroll
        for (int k = 0; k < 4; k++) {
            v[k] = wg[k*4+0]*__ldg(xc + idx[k*4+0])
                 + wg[k*4+1]*__ldg(xc + idx[k*4+1])
                 + wg[k*4+2]*__ldg(xc + idx[k*4+2])
                 + wg[k*4+3]*__ldg(xc + idx[k*4+3]);
        }
        *(float2*)(oc + ob)       = make_float2(v[0], v[1]);
        *(float2*)(oc + ob + 640) = make_float2(v[2], v[3]);
    }
}

// ---------------- launch ------------------------------------------------------
extern "C" void kernel_launch(void* const* d_in, const int* in_sizes, int n_in,
                              void* d_out, int out_size) {
    const float* x    = (const float*)d_in[0];
    const float* qry  = (const float*)d_in[1];
    const float* ref  = (const float*)d_in[2];
    const float* c1w  = (const float*)d_in[3];
    const float* c1b  = (const float*)d_in[4];
    const float* r1w1 = (const float*)d_in[5];
    const float* r1b1 = (const float*)d_in[6];
    const float* r1w2 = (const float*)d_in[7];
    const float* r1b2 = (const float*)d_in[8];
    const float* p1w  = (const float*)d_in[9];
    const float* p1b  = (const float*)d_in[10];
    const float* prw1 = (const float*)d_in[11];
    const float* prb1 = (const float*)d_in[12];
    const float* prw2 = (const float*)d_in[13];
    const float* prb2 = (const float*)d_in[14];
    const float* p2w  = (const float*)d_in[15];
    const float* p2b  = (const float*)d_in[16];
    float* out = (float*)d_out;

    float *up, *feat, *buf1, *buf2, *hid, *w3t, *w5a, *w5b;
    cudaGetSymbolAddress((void**)&up,   g_up);
    cudaGetSymbolAddress((void**)&feat, g_feat);
    cudaGetSymbolAddress((void**)&buf1, g_buf1);
    cudaGetSymbolAddress((void**)&buf2, g_buf2);
    cudaGetSymbolAddress((void**)&hid,  g_hid);
    cudaGetSymbolAddress((void**)&w3t,  g_w3t);
    cudaGetSymbolAddress((void**)&w5a,  g_w5a);
    cudaGetSymbolAddress((void**)&w5b,  g_w5b);

    const int SM3    = C3_SMEM;                          // 44544 B
    const int SM5_3  = 2*(3*C5_CIS + 3*800)*4;           // 32256 B
    const int SM5_64 = 2*(4*C5_CIS + 4*800)*4;           // 43008 B
    cudaFuncSetAttribute(conv3_k<0>, cudaFuncAttributeMaxDynamicSharedMemorySize, SM3);
    cudaFuncSetAttribute(conv3_k<1>, cudaFuncAttributeMaxDynamicSharedMemorySize, SM3);
    cudaFuncSetAttribute(conv5_k<3,3>,  cudaFuncAttributeMaxDynamicSharedMemorySize, SM5_3);
    cudaFuncSetAttribute(conv5_k<64,4>, cudaFuncAttributeMaxDynamicSharedMemorySize, SM5_64);

    dim3 cg2(5, 80, 2);
    dim3 cg1(5, 80, 1);

    // 0. merged transpose + bicubic upsample
    tr_all_k<<<(36864 + 2400 + 51200 + 255)/256, 256>>>(
        r1w1, r1w2, prw1, prw2, c1w, p1w, w3t, w5a, w5b);
    bicubic_k<<<(3*HWSZ)/256, 256>>>(qry, up);

    // feature heads (dual image)
    conv5_k<3,3><<<cg2, 256, SM5_3>>>(ref, up, w5a, c1b, buf1, buf1 + 32*HWSZ);
    conv3_k<0><<<cg2, 256, SM3>>>(buf1, buf1 + 32*HWSZ, w3t, r1b1,
                                  nullptr, nullptr, buf2, buf2 + 32*HWSZ);
    conv3_k<1><<<cg2, 256, SM3>>>(buf2, buf2 + 32*HWSZ, w3t + 9216, r1b2,
                                  buf1, buf1 + 32*HWSZ, feat, feat + 32*HWSZ);

    // fusion head
    conv5_k<64,4><<<cg1, 256, SM5_64>>>(feat, feat, w5b, p1b, buf1, buf1);
    conv3_k<0><<<cg1, 256, SM3>>>(buf1, buf1, w3t + 2*9216, prb1, nullptr, nullptr, buf2, buf2);
    conv3_k<1><<<cg1, 256, SM3>>>(buf2, buf2, w3t + 3*9216, prb2, buf1, buf1, hid, hid);

    // sampler: 4-way channel split
    dim3 sgrid(HWSZ/256, 4);
    sampler_k<<<sgrid, 256>>>(hid, p2w, p2b, x, out);
}

// round 15
// speedup vs baseline: 1.0114x; 1.0114x over previous
#include <cuda_runtime.h>
#include <math.h>
#include <stdint.h>

#define HH 320
#define WW 320
#define HWSZ (320*320)

// ---------------- scratch (static device globals; no allocation) -------------
__device__ float g_up[3*HWSZ];
__device__ float g_feat[64*HWSZ];
__device__ float g_buf1[64*HWSZ];
__device__ float g_buf2[64*HWSZ];
__device__ float g_hid[32*HWSZ];
__device__ __align__(16) float g_w3t[4*9216];   // 4 transposed 3x3 32->32 [ci][k][co]
__device__ __align__(16) float g_w5a[3*800];    // conv1 5x5 3->32  [ci][k][co]
__device__ __align__(16) float g_w5b[64*800];   // p1    5x5 64->32 [ci][k][co]

typedef unsigned long long u64;

// ---------------- packed f32x2 helpers (sm_103a FFMA2) -----------------------
__device__ __forceinline__ u64 pack2(float a, float b) {
    u64 r; asm("mov.b64 %0,{%1,%2};" : "=l"(r) : "f"(a), "f"(b)); return r;
}
__device__ __forceinline__ void unpack2(u64 v, float& a, float& b) {
    asm("mov.b64 {%0,%1},%2;" : "=f"(a), "=f"(b) : "l"(v));
}
__device__ __forceinline__ u64 fma2(u64 a, u64 b, u64 c) {
    u64 d; asm("fma.rn.f32x2 %0,%1,%2,%3;" : "=l"(d) : "l"(a), "l"(b), "l"(c)); return d;
}

// ---------------- cp.async helpers -------------------------------------------
__device__ __forceinline__ void cp4(uint32_t s, const float* g, bool ok) {
    int sz = ok ? 4 : 0;
    asm volatile("cp.async.ca.shared.global [%0], [%1], 4, %2;"
                 :: "r"(s), "l"(g), "r"(sz) : "memory");
}
__device__ __forceinline__ void cp16(uint32_t s, const float4* g) {
    asm volatile("cp.async.cg.shared.global [%0], [%1], 16;"
                 :: "r"(s), "l"(g) : "memory");
}
#define CP_COMMIT() asm volatile("cp.async.commit_group;" ::: "memory")
#define CP_WAIT(n)  asm volatile("cp.async.wait_group %0;" :: "n"(n) : "memory")

// ---------------- merged weight transpose pre-kernel --------------------------
__global__ void tr_all_k(const float* __restrict__ w0, const float* __restrict__ w1,
                         const float* __restrict__ w2, const float* __restrict__ w3,
                         const float* __restrict__ wa, const float* __restrict__ wb,
                         float* __restrict__ d3, float* __restrict__ da,
                         float* __restrict__ db) {
    int i = blockIdx.x*256 + threadIdx.x;
    if (i < 36864) {
        int n = i / 9216, e = i % 9216;
        const float* srcs[4] = {w0, w1, w2, w3};
        int co = e / 288, rem = e % 288, ci = rem / 9, k = rem % 9;
        d3[n*9216 + ci*288 + k*32 + co] = srcs[n][e];
    } else if (i < 36864 + 2400) {
        int e = i - 36864;
        int co = e / 75, rem = e % 75, ci = rem / 25, k = rem % 25;
        da[ci*800 + k*32 + co] = wa[e];
    } else if (i < 36864 + 2400 + 51200) {
        int e = i - 36864 - 2400;
        int co = e / 1600, rem = e % 1600, ci = rem / 25, k = rem % 25;
        db[ci*800 + k*32 + co] = wb[e];
    }
}

// ---------------- bicubic x2 (A = -0.75) -------------------------------------
__device__ __forceinline__ float cubicw(float t) {
    t = fabsf(t);
    if (t <= 1.0f) return ((1.25f*t - 2.25f)*t)*t + 1.0f;
    if (t <  2.0f) return -0.75f*((((t - 5.0f)*t + 8.0f)*t) - 4.0f);
    return 0.0f;
}

__global__ void bicubic_k(const float* __restrict__ q, float* __restrict__ o) {
    int idx = blockIdx.x*256 + threadIdx.x;
    int ox = idx % 320;
    int t  = idx / 320;
    int oy = t % 320;
    int c  = t / 320;
    float sy = (oy + 0.5f)*0.5f - 0.5f;
    float sx = (ox + 0.5f)*0.5f - 0.5f;
    int iy0 = (int)floorf(sy), ix0 = (int)floorf(sx);
    float wy[4], wx[4]; int jy[4], jx[4];
    #pragma unroll
    for (int k = 0; k < 4; k++) {
        int ty = iy0 - 1 + k;
        wy[k] = cubicw(sy - (float)ty);
        jy[k] = min(max(ty, 0), 159);
        int tx = ix0 - 1 + k;
        wx[k] = cubicw(sx - (float)tx);
        jx[k] = min(max(tx, 0), 159);
    }
    const float* qc = q + c*160*160;
    float s = 0.0f;
    #pragma unroll
    for (int yy = 0; yy < 4; yy++) {
        float acc = 0.0f;
        #pragma unroll
        for (int xx = 0; xx < 4; xx++)
            acc += wx[xx]*__ldg(qc + jy[yy]*160 + jx[xx]);
        s += wy[yy]*acc;
    }
    o[idx] = s;
}

// ---------------- 3x3 conv, 32->32, pad 1, dual image ------------------------
// tile 64x4; thread = 4 px x 8 co; cp.async double-buffered; 4 blocks/SM
#define C3_CHUNK 8
#define C3_RS   68
#define C3_CIS  (6*C3_RS)                    // 408
#define C3_BIN  (C3_CHUNK*C3_CIS)            // 3264
#define C3_BW   (C3_CHUNK*288)               // 2304
#define C3_BUF  (C3_BIN + C3_BW)             // 5568 floats
#define C3_SMEM (2*C3_BUF*4)                 // 44544 B

template<int MODE>
__global__ void __launch_bounds__(256, 4) conv3_k(
    const float* __restrict__ in0, const float* __restrict__ in1,
    const float* __restrict__ wtT, const float* __restrict__ bs,
    const float* __restrict__ sk0, const float* __restrict__ sk1,
    float* __restrict__ out0, float* __restrict__ out1)
{
    extern __shared__ float sm[];
    const uint32_t smem0 = (uint32_t)__cvta_generic_to_shared(sm);
    const float* in = blockIdx.z ? in1 : in0;
    const float* sk = blockIdx.z ? sk1 : sk0;
    float* out      = blockIdx.z ? out1 : out0;
    const int tid = threadIdx.x;
    const int txg = tid & 15;
    const int ty  = (tid >> 4) & 3;
    const int cog = tid >> 6;
    const int ox0 = blockIdx.x*64, oy0 = blockIdx.y*4;

    const int r1 = tid / 66,        c1 = tid % 66;
    const int r2 = (tid+256) / 66,  c2 = (tid+256) % 66;
    const bool has2 = tid < 140;
    const int y1 = oy0 - 1 + r1, x1 = ox0 - 1 + c1;
    const int y2 = oy0 - 1 + r2, x2 = ox0 - 1 + c2;
    const bool ok1 = (y1 >= 0 && y1 < HH && x1 >= 0 && x1 < WW);
    const bool ok2 = has2 && (y2 >= 0 && y2 < HH && x2 >= 0 && x2 < WW);
    const int g1 = ok1 ? (y1*WW + x1) : 0;
    const int g2 = ok2 ? (y2*WW + x2) : 0;
    const int so1 = r1*C3_RS + c1;
    const int so2 = r2*C3_RS + c2;

    auto stage = [&](int nb, int c0) {
        uint32_t sb = smem0 + nb*(C3_BUF*4);
        const float* ip1 = in + c0*HWSZ + g1;
        uint32_t d1 = sb + so1*4;
        #pragma unroll
        for (int ci = 0; ci < C3_CHUNK; ci++)
            cp4(d1 + ci*(C3_CIS*4), ip1 + ci*HWSZ, ok1);
        if (has2) {
            const float* ip2 = in + c0*HWSZ + g2;
            uint32_t d2 = sb + so2*4;
            #pragma unroll
            for (int ci = 0; ci < C3_CHUNK; ci++)
                cp4(d2 + ci*(C3_CIS*4), ip2 + ci*HWSZ, ok2);
        }
        const float4* wsrc = (const float4*)(wtT + c0*288);
        uint32_t wdst = sb + C3_BIN*4;
        cp16(wdst + tid*16,        wsrc + tid);
        cp16(wdst + (tid+256)*16,  wsrc + tid + 256);
        if (tid < 64) cp16(wdst + (tid+512)*16, wsrc + tid + 512);
    };

    u64 acc[4][4];
    #pragma unroll
    for (int cp = 0; cp < 4; cp++) {
        u64 b = pack2(__ldg(bs + cog*8 + 2*cp), __ldg(bs + cog*8 + 2*cp + 1));
        #pragma unroll
        for (int p = 0; p < 4; p++) acc[p][cp] = b;
    }

    stage(0, 0);
    CP_COMMIT();

    const int NCH = 32/C3_CHUNK;
    for (int ch = 0; ch < NCH; ch++) {
        int nb = ch & 1;
        if (ch + 1 < NCH) {
            stage(nb ^ 1, (ch+1)*C3_CHUNK);
            CP_COMMIT();
            CP_WAIT(1);
        } else {
            CP_WAIT(0);
        }
        __syncthreads();

        const float* s_in = sm + nb*C3_BUF;
        const float* s_w  = s_in + C3_BIN;
        for (int ci = 0; ci < C3_CHUNK; ci++) {
            const float* base = s_in + ci*C3_CIS + ty*C3_RS + txg*4;
            const float* wb   = s_w + ci*288 + cog*8;
            #pragma unroll
            for (int ky = 0; ky < 3; ky++) {
                const float* rp = base + ky*C3_RS;
                float4 v4 = *(const float4*)rp;
                float2 v2 = *(const float2*)(rp + 4);
                u64 vp[6];
                vp[0]=pack2(v4.x,v4.x); vp[1]=pack2(v4.y,v4.y); vp[2]=pack2(v4.z,v4.z);
                vp[3]=pack2(v4.w,v4.w); vp[4]=pack2(v2.x,v2.x); vp[5]=pack2(v2.y,v2.y);
                #pragma unroll
                for (int kx = 0; kx < 3; kx++) {
                    const ulonglong2* wq = (const ulonglong2*)(wb + (ky*3 + kx)*32);
                    ulonglong2 w0 = wq[0], w1 = wq[1];
                    u64 w[4] = {w0.x, w0.y, w1.x, w1.y};
                    #pragma unroll
                    for (int p = 0; p < 4; p++)
                        #pragma unroll
                        for (int cp = 0; cp < 4; cp++)
                            acc[p][cp] = fma2(vp[p+kx], w[cp], acc[p][cp]);
                }
            }
        }
        __syncthreads();
    }

    int o = (oy0 + ty)*WW + ox0 + txg*4;
    #pragma unroll
    for (int cp = 0; cp < 4; cp++) {
        int coe = cog*8 + 2*cp;
        float4 ve, vo;
        unpack2(acc[0][cp], ve.x, vo.x);
        unpack2(acc[1][cp], ve.y, vo.y);
        unpack2(acc[2][cp], ve.z, vo.z);
        unpack2(acc[3][cp], ve.w, vo.w);
        if (MODE == 0) {
            ve.x=fmaxf(ve.x,0.f); ve.y=fmaxf(ve.y,0.f); ve.z=fmaxf(ve.z,0.f); ve.w=fmaxf(ve.w,0.f);
            vo.x=fmaxf(vo.x,0.f); vo.y=fmaxf(vo.y,0.f); vo.z=fmaxf(vo.z,0.f); vo.w=fmaxf(vo.w,0.f);
        } else {
            float4 se = *(const float4*)(sk + coe*HWSZ + o);
            float4 so = *(const float4*)(sk + (coe+1)*HWSZ + o);
            ve.x+=se.x; ve.y+=se.y; ve.z+=se.z; ve.w+=se.w;
            vo.x+=so.x; vo.y+=so.y; vo.z+=so.z; vo.w+=so.w;
            ve.x=(ve.x>=0.f)?ve.x:0.2f*ve.x; ve.y=(ve.y>=0.f)?ve.y:0.2f*ve.y;
            ve.z=(ve.z>=0.f)?ve.z:0.2f*ve.z; ve.w=(ve.w>=0.f)?ve.w:0.2f*ve.w;
            vo.x=(vo.x>=0.f)?vo.x:0.2f*vo.x; vo.y=(vo.y>=0.f)?vo.y:0.2f*vo.y;
            vo.z=(vo.z>=0.f)?vo.z:0.2f*vo.z; vo.w=(vo.w>=0.f)?vo.w:0.2f*vo.w;
        }
        *(float4*)(out + coe*HWSZ + o)     = ve;
        *(float4*)(out + (coe+1)*HWSZ + o) = vo;
    }
}

// ---------------- 5x5 conv, CIN->32, pad 2, lrelu, dual image ----------------
// tile 64x4; thread = 4 px x 8 co; 3 blocks/SM (reverted: 4 forces spills)
#define C5_RS  68
#define C5_CIS (8*C5_RS)    // 544

template<int CIN, int CHUNK>
__global__ void __launch_bounds__(256, 3) conv5_k(
    const float* __restrict__ in0, const float* __restrict__ in1,
    const float* __restrict__ wtT, const float* __restrict__ bs,
    float* __restrict__ out0, float* __restrict__ out1)
{
    constexpr int BIN = CHUNK*C5_CIS;
    constexpr int BW  = CHUNK*800;
    constexpr int BUF = BIN + BW;
    extern __shared__ float sm[];
    const uint32_t smem0 = (uint32_t)__cvta_generic_to_shared(sm);
    const float* in = blockIdx.z ? in1 : in0;
    float* out      = blockIdx.z ? out1 : out0;
    const int tid = threadIdx.x;
    const int txg = tid & 15;
    const int ty  = (tid >> 4) & 3;
    const int cog = tid >> 6;
    const int ox0 = blockIdx.x*64, oy0 = blockIdx.y*4;

    const int ir[3] = { tid/68, (tid+256)/68, (tid+512)/68 };
    const int ic[3] = { tid%68, (tid+256)%68, (tid+512)%68 };
    const bool ihas[3] = { true, true, tid < 32 };
    bool iok[3]; int ig[3], iso[3];
    #pragma unroll
    for (int j = 0; j < 3; j++) {
        int y = oy0 - 2 + ir[j], x = ox0 - 2 + ic[j];
        iok[j] = ihas[j] && (y >= 0 && y < HH && x >= 0 && x < WW);
        ig[j]  = iok[j] ? (y*WW + x) : 0;
        iso[j] = ir[j]*C5_RS + ic[j];
    }

    auto stage = [&](int nb, int c0) {
        uint32_t sb = smem0 + nb*(BUF*4);
        #pragma unroll
        for (int j = 0; j < 3; j++) {
            if (!ihas[j]) continue;
            const float* ip = in + c0*HWSZ + ig[j];
            uint32_t d = sb + iso[j]*4;
            #pragma unroll
            for (int ci = 0; ci < CHUNK; ci++)
                cp4(d + ci*(C5_CIS*4), ip + ci*HWSZ, iok[j]);
        }
        const float4* wsrc = (const float4*)(wtT + c0*800);
        uint32_t wdst = sb + BIN*4;
        #pragma unroll
        for (int j = 0; j < (CHUNK*200 + 255)/256; j++) {
            int i = tid + j*256;
            if (i < CHUNK*200) cp16(wdst + i*16, wsrc + i);
        }
    };

    u64 acc[4][4];
    #pragma unroll
    for (int cp = 0; cp < 4; cp++) {
        u64 b = pack2(__ldg(bs + cog*8 + 2*cp), __ldg(bs + cog*8 + 2*cp + 1));
        #pragma unroll
        for (int p = 0; p < 4; p++) acc[p][cp] = b;
    }

    stage(0, 0);
    CP_COMMIT();

    constexpr int NCH = CIN/CHUNK;
    for (int ch = 0; ch < NCH; ch++) {
        int nb = ch & 1;
        if (ch + 1 < NCH) {
            stage(nb ^ 1, (ch+1)*CHUNK);
            CP_COMMIT();
            CP_WAIT(1);
        } else {
            CP_WAIT(0);
        }
        __syncthreads();

        const float* s_in = sm + nb*BUF;
        const float* s_w  = s_in + BIN;
        for (int ci = 0; ci < CHUNK; ci++) {
            const float* base = s_in + ci*C5_CIS + ty*C5_RS + txg*4;
            const float* wb   = s_w + ci*800 + cog*8;
            #pragma unroll
            for (int ky = 0; ky < 5; ky++) {
                const float* rp = base + ky*C5_RS;
                float4 a4 = *(const float4*)rp;
                float4 b4 = *(const float4*)(rp + 4);
                u64 vp[8];
                vp[0]=pack2(a4.x,a4.x); vp[1]=pack2(a4.y,a4.y); vp[2]=pack2(a4.z,a4.z);
                vp[3]=pack2(a4.w,a4.w); vp[4]=pack2(b4.x,b4.x); vp[5]=pack2(b4.y,b4.y);
                vp[6]=pack2(b4.z,b4.z); vp[7]=pack2(b4.w,b4.w);
                #pragma unroll
                for (int kx = 0; kx < 5; kx++) {
                    const ulonglong2* wq = (const ulonglong2*)(wb + (ky*5 + kx)*32);
                    ulonglong2 w0 = wq[0], w1 = wq[1];
                    u64 w[4] = {w0.x, w0.y, w1.x, w1.y};
                    #pragma unroll
                    for (int p = 0; p < 4; p++)
                        #pragma unroll
                        for (int cp = 0; cp < 4; cp++)
                            acc[p][cp] = fma2(vp[p+kx], w[cp], acc[p][cp]);
                }
            }
        }
        __syncthreads();
    }

    int o = (oy0 + ty)*WW + ox0 + txg*4;
    #pragma unroll
    for (int cp = 0; cp < 4; cp++) {
        int coe = cog*8 + 2*cp;
        float4 ve, vo;
        unpack2(acc[0][cp], ve.x, vo.x);
        unpack2(acc[1][cp], ve.y, vo.y);
        unpack2(acc[2][cp], ve.z, vo.z);
        unpack2(acc[3][cp], ve.w, vo.w);
        ve.x=(ve.x>=0.f)?ve.x:0.2f*ve.x; ve.y=(ve.y>=0.f)?ve.y:0.2f*ve.y;
        ve.z=(ve.z>=0.f)?ve.z:0.2f*ve.z; ve.w=(ve.w>=0.f)?ve.w:0.2f*ve.w;
        vo.x=(vo.x>=0.f)?vo.x:0.2f*vo.x; vo.y=(vo.y>=0.f)?vo.y:0.2f*vo.y;
        vo.z=(vo.z>=0.f)?vo.z:0.2f*vo.z; vo.w=(vo.w>=0.f)?vo.w:0.2f*vo.w;
        *(float4*)(out + coe*HWSZ + o)     = ve;
        *(float4*)(out + (coe+1)*HWSZ + o) = vo;
    }
}

// ---------------- fused 1x1 affine head + deformable sampler (4-way split) ----
__device__ __forceinline__ int reflect_idx(int i) {
    int r = i - 1;
    r = (r < 0) ? -r : r;
    r = (r > 319) ? (638 - r) : r;
    return r;
}

__global__ void sampler_k(const float* __restrict__ hid, const float* __restrict__ w2,
                          const float* __restrict__ b2, const float* __restrict__ x,
                          float* __restrict__ out) {
    __shared__ float s_w2[96];
    int tid = threadIdx.x;
    if (tid < 96) s_w2[tid] = w2[tid];
    __syncthreads();
    int p = blockIdx.x*256 + tid;
    int h = p / WW, w = p % WW;
    int cbase = blockIdx.y*16;

    float a0 = __ldg(b2 + 0), a1 = __ldg(b2 + 1), a2 = __ldg(b2 + 2);
    #pragma unroll 4
    for (int c = 0; c < 32; c++) {
        float hv = hid[c*HWSZ + p];
        a0 += hv*s_w2[c];
        a1 += hv*s_w2[32 + c];
        a2 += hv*s_w2[64 + c];
    }
    a0 = fminf(fmaxf(a0 + 1.0f, -3.0f), 3.0f);
    a1 = fminf(fmaxf(a1 + 1.0f, -3.0f), 3.0f);
    a2 = fminf(fmaxf(a2 + 1.0f, -3.0f), 3.0f);
    float th = (a2 - 1.0f)*1.0472f;
    float ct = cosf(th), st = sinf(th);

    int   idx[16];
    float wg[16];
    #pragma unroll
    for (int k = 0; k < 4; k++) {
        float pnx = (k & 2) ? 0.5f : -0.5f;
        float pny = (k & 1) ? 0.5f : -0.5f;
        float px = pnx*a0, py = pny*a1;
        float rx = px*ct - py*st;
        float ry = px*st + py*ct;
        float p_x = rx + 0.5f + (float)(h + 1);
        float p_y = ry + 0.5f + (float)(w + 1);
        float ltx = floorf(p_x), lty = floorf(p_y);
        float ltxc = fminf(fmaxf(ltx,        0.0f), 321.0f);
        float ltyc = fminf(fmaxf(lty,        0.0f), 321.0f);
        float rbxc = fminf(fmaxf(ltx + 1.0f, 0.0f), 321.0f);
        float rbyc = fminf(fmaxf(lty + 1.0f, 0.0f), 321.0f);
        float pxc  = fminf(fmaxf(p_x,        0.0f), 321.0f);
        float pyc  = fminf(fmaxf(p_y,        0.0f), 321.0f);
        float wlx = 1.0f + ltxc - pxc;
        float wrx = 1.0f - (rbxc - pxc);
        float wly = 1.0f + ltyc - pyc;
        float wry = 1.0f - (rbyc - pyc);
        int rl = reflect_idx((int)ltxc);
        int rr = reflect_idx((int)rbxc);
        int cl = reflect_idx((int)ltyc);
        int cr = reflect_idx((int)rbyc);
        idx[k*4+0] = rl*WW + cl;  wg[k*4+0] = wlx*wly;
        idx[k*4+1] = rr*WW + cr;  wg[k*4+1] = wrx*wry;
        idx[k*4+2] = rl*WW + cr;  wg[k*4+2] = wlx*wry;
        idx[k*4+3] = rr*WW + cl;  wg[k*4+3] = wrx*wly;
    }

    int ob = (2*h)*640 + 2*w;
    for (int c = cbase; c < cbase + 16; c++) {
        const float* xc = x + c*HWSZ;
        float* oc = out + c*640*640;
        float v[4];
        #pragma unroll
        for (int k = 0; k < 4; k++) {
            v[k] = wg[k*4+0]*__ldg(xc + idx[k*4+0])
                 + wg[k*4+1]*__ldg(xc + idx[k*4+1])
                 + wg[k*4+2]*__ldg(xc + idx[k*4+2])
                 + wg[k*4+3]*__ldg(xc + idx[k*4+3]);
        }
        *(float2*)(oc + ob)       = make_float2(v[0], v[1]);
        *(float2*)(oc + ob + 640) = make_float2(v[2], v[3]);
    }
}

// ---------------- launch ------------------------------------------------------
extern "C" void kernel_launch(void* const* d_in, const int* in_sizes, int n_in,
                              void* d_out, int out_size) {
    const float* x    = (const float*)d_in[0];
    const float* qry  = (const float*)d_in[1];
    const float* ref  = (const float*)d_in[2];
    const float* c1w  = (const float*)d_in[3];
    const float* c1b  = (const float*)d_in[4];
    const float* r1w1 = (const float*)d_in[5];
    const float* r1b1 = (const float*)d_in[6];
    const float* r1w2 = (const float*)d_in[7];
    const float* r1b2 = (const float*)d_in[8];
    const float* p1w  = (const float*)d_in[9];
    const float* p1b  = (const float*)d_in[10];
    const float* prw1 = (const float*)d_in[11];
    const float* prb1 = (const float*)d_in[12];
    const float* prw2 = (const float*)d_in[13];
    const float* prb2 = (const float*)d_in[14];
    const float* p2w  = (const float*)d_in[15];
    const float* p2b  = (const float*)d_in[16];
    float* out = (float*)d_out;

    float *up, *feat, *buf1, *buf2, *hid, *w3t, *w5a, *w5b;
    cudaGetSymbolAddress((void**)&up,   g_up);
    cudaGetSymbolAddress((void**)&feat, g_feat);
    cudaGetSymbolAddress((void**)&buf1, g_buf1);
    cudaGetSymbolAddress((void**)&buf2, g_buf2);
    cudaGetSymbolAddress((void**)&hid,  g_hid);
    cudaGetSymbolAddress((void**)&w3t,  g_w3t);
    cudaGetSymbolAddress((void**)&w5a,  g_w5a);
    cudaGetSymbolAddress((void**)&w5b,  g_w5b);

    const int SM3    = C3_SMEM;                          // 44544 B
    const int SM5_3  = 2*(3*C5_CIS + 3*800)*4;           // 32256 B
    const int SM5_64 = 2*(4*C5_CIS + 4*800)*4;           // 43008 B
    cudaFuncSetAttribute(conv3_k<0>, cudaFuncAttributeMaxDynamicSharedMemorySize, SM3);
    cudaFuncSetAttribute(conv3_k<1>, cudaFuncAttributeMaxDynamicSharedMemorySize, SM3);
    cudaFuncSetAttribute(conv5_k<3,3>,  cudaFuncAttributeMaxDynamicSharedMemorySize, SM5_3);
    cudaFuncSetAttribute(conv5_k<64,4>, cudaFuncAttributeMaxDynamicSharedMemorySize, SM5_64);

    dim3 cg2(5, 80, 2);
    dim3 cg1(5, 80, 1);

    // 0. merged transpose + bicubic upsample
    tr_all_k<<<(36864 + 2400 + 51200 + 255)/256, 256>>>(
        r1w1, r1w2, prw1, prw2, c1w, p1w, w3t, w5a, w5b);
    bicubic_k<<<(3*HWSZ)/256, 256>>>(qry, up);

    // feature heads (dual image)
    conv5_k<3,3><<<cg2, 256, SM5_3>>>(ref, up, w5a, c1b, buf1, buf1 + 32*HWSZ);
    conv3_k<0><<<cg2, 256, SM3>>>(buf1, buf1 + 32*HWSZ, w3t, r1b1,
                                  nullptr, nullptr, buf2, buf2 + 32*HWSZ);
    conv3_k<1><<<cg2, 256, SM3>>>(buf2, buf2 + 32*HWSZ, w3t + 9216, r1b2,
                                  buf1, buf1 + 32*HWSZ, feat, feat + 32*HWSZ);

    // fusion head
    conv5_k<64,4><<<cg1, 256, SM5_64>>>(feat, feat, w5b, p1b, buf1, buf1);
    conv3_k<0><<<cg1, 256, SM3>>>(buf1, buf1, w3t + 2*9216, prb1, nullptr, nullptr, buf2, buf2);
    conv3_k<1><<<cg1, 256, SM3>>>(buf2, buf2, w3t + 3*9216, prb2, buf1, buf1, hid, hid);

    // sampler: 4-way channel split
    dim3 sgrid(HWSZ/256, 4);
    sampler_k<<<sgrid, 256>>>(hid, p2w, p2b, x, out);
}